// round 1
// baseline (speedup 1.0000x reference)
#include <cuda_runtime.h>
#include <math.h>

#define D_MODEL 1024
#define N_HEADS 16
#define D_KH    64
#define B_SZ    4
#define T_SEQ   2048
#define M_ROWS  (B_SZ * T_SEQ)   // 8192

// Scratch (allocation-free rule: __device__ globals)
__device__ float g_Q[M_ROWS * D_MODEL];
__device__ float g_K[M_ROWS * D_MODEL];
__device__ float g_V[M_ROWS * D_MODEL];
__device__ float g_O[M_ROWS * D_MODEL];

// ---------------------------------------------------------------------------
// C[m][n] = sum_k A[m][k] * Bw[n][k] + bias[n]
// 64x64x64 tiles, 256 threads, 4x4 microtile per thread.
// Smem staged transposed so inner loop = 2x LDS.128 + 16 FFMA.
// ---------------------------------------------------------------------------
__global__ void __launch_bounds__(256) gemm_bt_bias(
    const float* __restrict__ A, const float* __restrict__ Bw,
    const float* __restrict__ bias, float* __restrict__ C,
    int M, int N, int K)
{
    __shared__ float As[64][68];  // [k][m]
    __shared__ float Bs[64][68];  // [k][n]

    const int tid = threadIdx.x;
    const int tx  = tid & 15;     // n-dim microtile
    const int ty  = tid >> 4;     // m-dim microtile
    const int bm  = blockIdx.y * 64;
    const int bn  = blockIdx.x * 64;

    float acc[4][4] = {};

    for (int k0 = 0; k0 < K; k0 += 64) {
#pragma unroll
        for (int i = 0; i < 4; i++) {
            int r = ty + i * 16;
            float4 a = *(const float4*)&A [(size_t)(bm + r) * K + k0 + tx * 4];
            float4 b = *(const float4*)&Bw[(size_t)(bn + r) * K + k0 + tx * 4];
            As[tx * 4 + 0][r] = a.x; As[tx * 4 + 1][r] = a.y;
            As[tx * 4 + 2][r] = a.z; As[tx * 4 + 3][r] = a.w;
            Bs[tx * 4 + 0][r] = b.x; Bs[tx * 4 + 1][r] = b.y;
            Bs[tx * 4 + 2][r] = b.z; Bs[tx * 4 + 3][r] = b.w;
        }
        __syncthreads();

#pragma unroll
        for (int k = 0; k < 64; k++) {
            float4 av = *(const float4*)&As[k][ty * 4];
            float4 bv = *(const float4*)&Bs[k][tx * 4];
            acc[0][0] += av.x * bv.x; acc[0][1] += av.x * bv.y;
            acc[0][2] += av.x * bv.z; acc[0][3] += av.x * bv.w;
            acc[1][0] += av.y * bv.x; acc[1][1] += av.y * bv.y;
            acc[1][2] += av.y * bv.z; acc[1][3] += av.y * bv.w;
            acc[2][0] += av.z * bv.x; acc[2][1] += av.z * bv.y;
            acc[2][2] += av.z * bv.z; acc[2][3] += av.z * bv.w;
            acc[3][0] += av.w * bv.x; acc[3][1] += av.w * bv.y;
            acc[3][2] += av.w * bv.z; acc[3][3] += av.w * bv.w;
        }
        __syncthreads();
    }

#pragma unroll
    for (int r = 0; r < 4; r++) {
        int m = bm + ty * 4 + r;
#pragma unroll
        for (int c = 0; c < 4; c++) {
            int n = bn + tx * 4 + c;
            C[(size_t)m * N + n] = acc[r][c] + bias[n];
        }
    }
}

// ---------------------------------------------------------------------------
// Causal flash attention (fp32, online softmax).
// Grid: (T/64, B*H). Block = 64 query rows of one head. 256 threads, 4x4
// microtiles for both S (64x64) and O (64x64).
// ---------------------------------------------------------------------------
#define SM_STRIDE 68
#define SM_TILE   (64 * SM_STRIDE)

__global__ void __launch_bounds__(256) attn_causal()
{
    extern __shared__ float sm[];
    float* Qs = sm;                // [d][i]  (transposed)
    float* Ks = sm + SM_TILE;      // [d][j]  (transposed)
    float* Vs = sm + 2 * SM_TILE;  // [j][c]  (natural)
    float* Ps = sm + 3 * SM_TILE;  // [j][i]  (transposed)

    const int qb = blockIdx.x;              // query block 0..31
    const int bh = blockIdx.y;              // 0..63
    const int b  = bh / N_HEADS;
    const int h  = bh % N_HEADS;

    const int tid = threadIdx.x;
    const int tx  = tid & 15;
    const int ty  = tid >> 4;

    const float scale = 0.125f;  // 1/sqrt(64)

    const float* Qg = g_Q + (size_t)(b * T_SEQ) * D_MODEL + h * D_KH;
    const float* Kg = g_K + (size_t)(b * T_SEQ) * D_MODEL + h * D_KH;
    const float* Vg = g_V + (size_t)(b * T_SEQ) * D_MODEL + h * D_KH;

    // Load Q tile (64 rows x 64 dims), transposed into Qs[d][i]
#pragma unroll
    for (int i = 0; i < 4; i++) {
        int r = ty + i * 16;
        float4 q = *(const float4*)&Qg[(size_t)(qb * 64 + r) * D_MODEL + tx * 4];
        Qs[(tx * 4 + 0) * SM_STRIDE + r] = q.x;
        Qs[(tx * 4 + 1) * SM_STRIDE + r] = q.y;
        Qs[(tx * 4 + 2) * SM_STRIDE + r] = q.z;
        Qs[(tx * 4 + 3) * SM_STRIDE + r] = q.w;
    }
    __syncthreads();

    float m_i[4], l_i[4];
    float O[4][4] = {};
#pragma unroll
    for (int r = 0; r < 4; r++) { m_i[r] = -INFINITY; l_i[r] = 0.f; }

    for (int kb = 0; kb <= qb; kb++) {
        // Load K (transposed) and V (natural) tiles
#pragma unroll
        for (int i = 0; i < 4; i++) {
            int r = ty + i * 16;
            float4 kv = *(const float4*)&Kg[(size_t)(kb * 64 + r) * D_MODEL + tx * 4];
            Ks[(tx * 4 + 0) * SM_STRIDE + r] = kv.x;
            Ks[(tx * 4 + 1) * SM_STRIDE + r] = kv.y;
            Ks[(tx * 4 + 2) * SM_STRIDE + r] = kv.z;
            Ks[(tx * 4 + 3) * SM_STRIDE + r] = kv.w;
            float4 vv = *(const float4*)&Vg[(size_t)(kb * 64 + r) * D_MODEL + tx * 4];
            *(float4*)&Vs[r * SM_STRIDE + tx * 4] = vv;
        }
        __syncthreads();

        // S = scale * Q K^T  (4x4 per thread)
        float s[4][4] = {};
#pragma unroll
        for (int d = 0; d < 64; d++) {
            float4 qv = *(const float4*)&Qs[d * SM_STRIDE + ty * 4];
            float4 kv = *(const float4*)&Ks[d * SM_STRIDE + tx * 4];
            s[0][0] += qv.x * kv.x; s[0][1] += qv.x * kv.y;
            s[0][2] += qv.x * kv.z; s[0][3] += qv.x * kv.w;
            s[1][0] += qv.y * kv.x; s[1][1] += qv.y * kv.y;
            s[1][2] += qv.y * kv.z; s[1][3] += qv.y * kv.w;
            s[2][0] += qv.z * kv.x; s[2][1] += qv.z * kv.y;
            s[2][2] += qv.z * kv.z; s[2][3] += qv.z * kv.w;
            s[3][0] += qv.w * kv.x; s[3][1] += qv.w * kv.y;
            s[3][2] += qv.w * kv.z; s[3][3] += qv.w * kv.w;
        }

        // scale + causal mask (only the diagonal block needs masking)
        if (kb == qb) {
#pragma unroll
            for (int r = 0; r < 4; r++) {
                int qrow = ty * 4 + r;
#pragma unroll
                for (int c = 0; c < 4; c++) {
                    int kcol = tx * 4 + c;
                    s[r][c] = (kcol <= qrow) ? s[r][c] * scale : -INFINITY;
                }
            }
        } else {
#pragma unroll
            for (int r = 0; r < 4; r++)
#pragma unroll
                for (int c = 0; c < 4; c++) s[r][c] *= scale;
        }

        // Online softmax per row; P stored transposed to Ps[j][i]
#pragma unroll
        for (int r = 0; r < 4; r++) {
            float mx = fmaxf(fmaxf(s[r][0], s[r][1]), fmaxf(s[r][2], s[r][3]));
#pragma unroll
            for (int o = 8; o >= 1; o >>= 1)
                mx = fmaxf(mx, __shfl_xor_sync(0xffffffffu, mx, o));
            float m_new = fmaxf(m_i[r], mx);
            float corr  = __expf(m_i[r] - m_new);
            float p0 = __expf(s[r][0] - m_new);
            float p1 = __expf(s[r][1] - m_new);
            float p2 = __expf(s[r][2] - m_new);
            float p3 = __expf(s[r][3] - m_new);
            float rs = p0 + p1 + p2 + p3;
#pragma unroll
            for (int o = 8; o >= 1; o >>= 1)
                rs += __shfl_xor_sync(0xffffffffu, rs, o);
            l_i[r] = l_i[r] * corr + rs;
            m_i[r] = m_new;
#pragma unroll
            for (int c = 0; c < 4; c++) O[r][c] *= corr;
            Ps[(tx * 4 + 0) * SM_STRIDE + ty * 4 + r] = p0;
            Ps[(tx * 4 + 1) * SM_STRIDE + ty * 4 + r] = p1;
            Ps[(tx * 4 + 2) * SM_STRIDE + ty * 4 + r] = p2;
            Ps[(tx * 4 + 3) * SM_STRIDE + ty * 4 + r] = p3;
        }
        __syncthreads();

        // O += P V
#pragma unroll
        for (int j = 0; j < 64; j++) {
            float4 pv = *(const float4*)&Ps[j * SM_STRIDE + ty * 4];
            float4 vv = *(const float4*)&Vs[j * SM_STRIDE + tx * 4];
            O[0][0] += pv.x * vv.x; O[0][1] += pv.x * vv.y;
            O[0][2] += pv.x * vv.z; O[0][3] += pv.x * vv.w;
            O[1][0] += pv.y * vv.x; O[1][1] += pv.y * vv.y;
            O[1][2] += pv.y * vv.z; O[1][3] += pv.y * vv.w;
            O[2][0] += pv.z * vv.x; O[2][1] += pv.z * vv.y;
            O[2][2] += pv.z * vv.z; O[2][3] += pv.z * vv.w;
            O[3][0] += pv.w * vv.x; O[3][1] += pv.w * vv.y;
            O[3][2] += pv.w * vv.z; O[3][3] += pv.w * vv.w;
        }
        __syncthreads();
    }

    // Write normalized output, heads re-merged: g_O[b*T + q][h*64 + c]
#pragma unroll
    for (int r = 0; r < 4; r++) {
        float inv_l = 1.0f / l_i[r];
        int qrow = qb * 64 + ty * 4 + r;
        float* dst = g_O + (size_t)(b * T_SEQ + qrow) * D_MODEL + h * D_KH + tx * 4;
        dst[0] = O[r][0] * inv_l;
        dst[1] = O[r][1] * inv_l;
        dst[2] = O[r][2] * inv_l;
        dst[3] = O[r][3] * inv_l;
    }
}

// ---------------------------------------------------------------------------
extern "C" void kernel_launch(void* const* d_in, const int* in_sizes, int n_in,
                              void* d_out, int out_size)
{
    const float* q   = (const float*)d_in[0];
    const float* k   = (const float*)d_in[1];
    const float* v   = (const float*)d_in[2];
    // d_in[3] = mask (bool causal tril) — causality is hardcoded in attn_causal
    const float* W_q = (const float*)d_in[4];
    const float* b_q = (const float*)d_in[5];
    const float* W_k = (const float*)d_in[6];
    const float* b_k = (const float*)d_in[7];
    const float* W_v = (const float*)d_in[8];
    const float* b_v = (const float*)d_in[9];
    const float* W_o = (const float*)d_in[10];
    const float* b_o = (const float*)d_in[11];
    float* out = (float*)d_out;

    float *pQ, *pK, *pV, *pO;
    cudaGetSymbolAddress((void**)&pQ, g_Q);
    cudaGetSymbolAddress((void**)&pK, g_K);
    cudaGetSymbolAddress((void**)&pV, g_V);
    cudaGetSymbolAddress((void**)&pO, g_O);

    const int attn_smem = 4 * SM_TILE * (int)sizeof(float);  // 69632 B
    cudaFuncSetAttribute(attn_causal, cudaFuncAttributeMaxDynamicSharedMemorySize,
                         attn_smem);

    dim3 gGrid(D_MODEL / 64, M_ROWS / 64);  // (16, 128)
    gemm_bt_bias<<<gGrid, 256>>>(q, W_q, b_q, pQ, M_ROWS, D_MODEL, D_MODEL);
    gemm_bt_bias<<<gGrid, 256>>>(k, W_k, b_k, pK, M_ROWS, D_MODEL, D_MODEL);
    gemm_bt_bias<<<gGrid, 256>>>(v, W_v, b_v, pV, M_ROWS, D_MODEL, D_MODEL);

    dim3 aGrid(T_SEQ / 64, B_SZ * N_HEADS);  // (32, 64)
    attn_causal<<<aGrid, 256, attn_smem>>>();

    gemm_bt_bias<<<gGrid, 256>>>(pO, W_o, b_o, out, M_ROWS, D_MODEL, D_MODEL);
}

// round 2
// speedup vs baseline: 1.0019x; 1.0019x over previous
#include <cuda_runtime.h>
#include <math.h>

#define D_MODEL 1024
#define N_HEADS 16
#define D_KH    64
#define B_SZ    4
#define T_SEQ   2048
#define M_ROWS  (B_SZ * T_SEQ)   // 8192

// Scratch (allocation-free rule: __device__ globals)
__device__ float g_Q[M_ROWS * D_MODEL];
__device__ float g_K[M_ROWS * D_MODEL];
__device__ float g_V[M_ROWS * D_MODEL];
__device__ float g_O[M_ROWS * D_MODEL];

// ---------------------------------------------------------------------------
// C[m][n] = sum_k A[m][k] * Bw[n][k] + bias[n]
// 64x64x64 tiles, 256 threads, 4x4 microtile per thread.
// Smem staged transposed so inner loop = 2x LDS.128 + 16 FFMA.
// ---------------------------------------------------------------------------
__global__ void __launch_bounds__(256) gemm_bt_bias(
    const float* __restrict__ A, const float* __restrict__ Bw,
    const float* __restrict__ bias, float* __restrict__ C,
    int M, int N, int K)
{
    __shared__ float As[64][68];  // [k][m]
    __shared__ float Bs[64][68];  // [k][n]

    const int tid = threadIdx.x;
    const int tx  = tid & 15;     // n-dim microtile
    const int ty  = tid >> 4;     // m-dim microtile
    const int bm  = blockIdx.y * 64;
    const int bn  = blockIdx.x * 64;

    float acc[4][4] = {};

    for (int k0 = 0; k0 < K; k0 += 64) {
#pragma unroll
        for (int i = 0; i < 4; i++) {
            int r = ty + i * 16;
            float4 a = *(const float4*)&A [(size_t)(bm + r) * K + k0 + tx * 4];
            float4 b = *(const float4*)&Bw[(size_t)(bn + r) * K + k0 + tx * 4];
            As[tx * 4 + 0][r] = a.x; As[tx * 4 + 1][r] = a.y;
            As[tx * 4 + 2][r] = a.z; As[tx * 4 + 3][r] = a.w;
            Bs[tx * 4 + 0][r] = b.x; Bs[tx * 4 + 1][r] = b.y;
            Bs[tx * 4 + 2][r] = b.z; Bs[tx * 4 + 3][r] = b.w;
        }
        __syncthreads();

#pragma unroll
        for (int k = 0; k < 64; k++) {
            float4 av = *(const float4*)&As[k][ty * 4];
            float4 bv = *(const float4*)&Bs[k][tx * 4];
            acc[0][0] += av.x * bv.x; acc[0][1] += av.x * bv.y;
            acc[0][2] += av.x * bv.z; acc[0][3] += av.x * bv.w;
            acc[1][0] += av.y * bv.x; acc[1][1] += av.y * bv.y;
            acc[1][2] += av.y * bv.z; acc[1][3] += av.y * bv.w;
            acc[2][0] += av.z * bv.x; acc[2][1] += av.z * bv.y;
            acc[2][2] += av.z * bv.z; acc[2][3] += av.z * bv.w;
            acc[3][0] += av.w * bv.x; acc[3][1] += av.w * bv.y;
            acc[3][2] += av.w * bv.z; acc[3][3] += av.w * bv.w;
        }
        __syncthreads();
    }

#pragma unroll
    for (int r = 0; r < 4; r++) {
        int m = bm + ty * 4 + r;
#pragma unroll
        for (int c = 0; c < 4; c++) {
            int n = bn + tx * 4 + c;
            C[(size_t)m * N + n] = acc[r][c] + bias[n];
        }
    }
}

// ---------------------------------------------------------------------------
// Causal flash attention (fp32, online softmax).
// Grid: (T/64, B*H). Block = 64 query rows of one head. 256 threads, 4x4
// microtiles for both S (64x64) and O (64x64).
// ---------------------------------------------------------------------------
#define SM_STRIDE 68
#define SM_TILE   (64 * SM_STRIDE)

__global__ void __launch_bounds__(256) attn_causal()
{
    extern __shared__ float sm[];
    float* Qs = sm;                // [d][i]  (transposed)
    float* Ks = sm + SM_TILE;      // [d][j]  (transposed)
    float* Vs = sm + 2 * SM_TILE;  // [j][c]  (natural)
    float* Ps = sm + 3 * SM_TILE;  // [j][i]  (transposed)

    const int qb = blockIdx.x;              // query block 0..31
    const int bh = blockIdx.y;              // 0..63
    const int b  = bh / N_HEADS;
    const int h  = bh % N_HEADS;

    const int tid = threadIdx.x;
    const int tx  = tid & 15;
    const int ty  = tid >> 4;

    const float scale = 0.125f;  // 1/sqrt(64)

    const float* Qg = g_Q + (size_t)(b * T_SEQ) * D_MODEL + h * D_KH;
    const float* Kg = g_K + (size_t)(b * T_SEQ) * D_MODEL + h * D_KH;
    const float* Vg = g_V + (size_t)(b * T_SEQ) * D_MODEL + h * D_KH;

    // Load Q tile (64 rows x 64 dims), transposed into Qs[d][i]
#pragma unroll
    for (int i = 0; i < 4; i++) {
        int r = ty + i * 16;
        float4 q = *(const float4*)&Qg[(size_t)(qb * 64 + r) * D_MODEL + tx * 4];
        Qs[(tx * 4 + 0) * SM_STRIDE + r] = q.x;
        Qs[(tx * 4 + 1) * SM_STRIDE + r] = q.y;
        Qs[(tx * 4 + 2) * SM_STRIDE + r] = q.z;
        Qs[(tx * 4 + 3) * SM_STRIDE + r] = q.w;
    }
    __syncthreads();

    float m_i[4], l_i[4];
    float O[4][4] = {};
#pragma unroll
    for (int r = 0; r < 4; r++) { m_i[r] = -INFINITY; l_i[r] = 0.f; }

    for (int kb = 0; kb <= qb; kb++) {
        // Load K (transposed) and V (natural) tiles
#pragma unroll
        for (int i = 0; i < 4; i++) {
            int r = ty + i * 16;
            float4 kv = *(const float4*)&Kg[(size_t)(kb * 64 + r) * D_MODEL + tx * 4];
            Ks[(tx * 4 + 0) * SM_STRIDE + r] = kv.x;
            Ks[(tx * 4 + 1) * SM_STRIDE + r] = kv.y;
            Ks[(tx * 4 + 2) * SM_STRIDE + r] = kv.z;
            Ks[(tx * 4 + 3) * SM_STRIDE + r] = kv.w;
            float4 vv = *(const float4*)&Vg[(size_t)(kb * 64 + r) * D_MODEL + tx * 4];
            *(float4*)&Vs[r * SM_STRIDE + tx * 4] = vv;
        }
        __syncthreads();

        // S = scale * Q K^T  (4x4 per thread)
        float s[4][4] = {};
#pragma unroll
        for (int d = 0; d < 64; d++) {
            float4 qv = *(const float4*)&Qs[d * SM_STRIDE + ty * 4];
            float4 kv = *(const float4*)&Ks[d * SM_STRIDE + tx * 4];
            s[0][0] += qv.x * kv.x; s[0][1] += qv.x * kv.y;
            s[0][2] += qv.x * kv.z; s[0][3] += qv.x * kv.w;
            s[1][0] += qv.y * kv.x; s[1][1] += qv.y * kv.y;
            s[1][2] += qv.y * kv.z; s[1][3] += qv.y * kv.w;
            s[2][0] += qv.z * kv.x; s[2][1] += qv.z * kv.y;
            s[2][2] += qv.z * kv.z; s[2][3] += qv.z * kv.w;
            s[3][0] += qv.w * kv.x; s[3][1] += qv.w * kv.y;
            s[3][2] += qv.w * kv.z; s[3][3] += qv.w * kv.w;
        }

        // scale + causal mask (only the diagonal block needs masking)
        if (kb == qb) {
#pragma unroll
            for (int r = 0; r < 4; r++) {
                int qrow = ty * 4 + r;
#pragma unroll
                for (int c = 0; c < 4; c++) {
                    int kcol = tx * 4 + c;
                    s[r][c] = (kcol <= qrow) ? s[r][c] * scale : -INFINITY;
                }
            }
        } else {
#pragma unroll
            for (int r = 0; r < 4; r++)
#pragma unroll
                for (int c = 0; c < 4; c++) s[r][c] *= scale;
        }

        // Online softmax per row; P stored transposed to Ps[j][i]
#pragma unroll
        for (int r = 0; r < 4; r++) {
            float mx = fmaxf(fmaxf(s[r][0], s[r][1]), fmaxf(s[r][2], s[r][3]));
#pragma unroll
            for (int o = 8; o >= 1; o >>= 1)
                mx = fmaxf(mx, __shfl_xor_sync(0xffffffffu, mx, o));
            float m_new = fmaxf(m_i[r], mx);
            float corr  = __expf(m_i[r] - m_new);
            float p0 = __expf(s[r][0] - m_new);
            float p1 = __expf(s[r][1] - m_new);
            float p2 = __expf(s[r][2] - m_new);
            float p3 = __expf(s[r][3] - m_new);
            float rs = p0 + p1 + p2 + p3;
#pragma unroll
            for (int o = 8; o >= 1; o >>= 1)
                rs += __shfl_xor_sync(0xffffffffu, rs, o);
            l_i[r] = l_i[r] * corr + rs;
            m_i[r] = m_new;
#pragma unroll
            for (int c = 0; c < 4; c++) O[r][c] *= corr;
            Ps[(tx * 4 + 0) * SM_STRIDE + ty * 4 + r] = p0;
            Ps[(tx * 4 + 1) * SM_STRIDE + ty * 4 + r] = p1;
            Ps[(tx * 4 + 2) * SM_STRIDE + ty * 4 + r] = p2;
            Ps[(tx * 4 + 3) * SM_STRIDE + ty * 4 + r] = p3;
        }
        __syncthreads();

        // O += P V
#pragma unroll
        for (int j = 0; j < 64; j++) {
            float4 pv = *(const float4*)&Ps[j * SM_STRIDE + ty * 4];
            float4 vv = *(const float4*)&Vs[j * SM_STRIDE + tx * 4];
            O[0][0] += pv.x * vv.x; O[0][1] += pv.x * vv.y;
            O[0][2] += pv.x * vv.z; O[0][3] += pv.x * vv.w;
            O[1][0] += pv.y * vv.x; O[1][1] += pv.y * vv.y;
            O[1][2] += pv.y * vv.z; O[1][3] += pv.y * vv.w;
            O[2][0] += pv.z * vv.x; O[2][1] += pv.z * vv.y;
            O[2][2] += pv.z * vv.z; O[2][3] += pv.z * vv.w;
            O[3][0] += pv.w * vv.x; O[3][1] += pv.w * vv.y;
            O[3][2] += pv.w * vv.z; O[3][3] += pv.w * vv.w;
        }
        __syncthreads();
    }

    // Write normalized output, heads re-merged: g_O[b*T + q][h*64 + c]
#pragma unroll
    for (int r = 0; r < 4; r++) {
        float inv_l = 1.0f / l_i[r];
        int qrow = qb * 64 + ty * 4 + r;
        float* dst = g_O + (size_t)(b * T_SEQ + qrow) * D_MODEL + h * D_KH + tx * 4;
        dst[0] = O[r][0] * inv_l;
        dst[1] = O[r][1] * inv_l;
        dst[2] = O[r][2] * inv_l;
        dst[3] = O[r][3] * inv_l;
    }
}

// ---------------------------------------------------------------------------
extern "C" void kernel_launch(void* const* d_in, const int* in_sizes, int n_in,
                              void* d_out, int out_size)
{
    const float* q   = (const float*)d_in[0];
    const float* k   = (const float*)d_in[1];
    const float* v   = (const float*)d_in[2];
    // d_in[3] = mask (bool causal tril) — causality is hardcoded in attn_causal
    const float* W_q = (const float*)d_in[4];
    const float* b_q = (const float*)d_in[5];
    const float* W_k = (const float*)d_in[6];
    const float* b_k = (const float*)d_in[7];
    const float* W_v = (const float*)d_in[8];
    const float* b_v = (const float*)d_in[9];
    const float* W_o = (const float*)d_in[10];
    const float* b_o = (const float*)d_in[11];
    float* out = (float*)d_out;

    float *pQ, *pK, *pV, *pO;
    cudaGetSymbolAddress((void**)&pQ, g_Q);
    cudaGetSymbolAddress((void**)&pK, g_K);
    cudaGetSymbolAddress((void**)&pV, g_V);
    cudaGetSymbolAddress((void**)&pO, g_O);

    const int attn_smem = 4 * SM_TILE * (int)sizeof(float);  // 69632 B
    cudaFuncSetAttribute(attn_causal, cudaFuncAttributeMaxDynamicSharedMemorySize,
                         attn_smem);

    dim3 gGrid(D_MODEL / 64, M_ROWS / 64);  // (16, 128)
    gemm_bt_bias<<<gGrid, 256>>>(q, W_q, b_q, pQ, M_ROWS, D_MODEL, D_MODEL);
    gemm_bt_bias<<<gGrid, 256>>>(k, W_k, b_k, pK, M_ROWS, D_MODEL, D_MODEL);
    gemm_bt_bias<<<gGrid, 256>>>(v, W_v, b_v, pV, M_ROWS, D_MODEL, D_MODEL);

    dim3 aGrid(T_SEQ / 64, B_SZ * N_HEADS);  // (32, 64)
    attn_causal<<<aGrid, 256, attn_smem>>>();

    gemm_bt_bias<<<gGrid, 256>>>(pO, W_o, b_o, out, M_ROWS, D_MODEL, D_MODEL);
}

// round 4
// speedup vs baseline: 1.7217x; 1.7184x over previous
#include <cuda_runtime.h>
#include <math.h>
#include <stdint.h>

#define D_MODEL 1024
#define N_HEADS 16
#define D_KH    64
#define B_SZ    4
#define T_SEQ   2048
#define M_ROWS  (B_SZ * T_SEQ)   // 8192

// Scratch (allocation-free rule: __device__ globals)
__device__ float g_Q[M_ROWS * D_MODEL];
__device__ float g_K[M_ROWS * D_MODEL];
__device__ float g_V[M_ROWS * D_MODEL];
__device__ float g_O[M_ROWS * D_MODEL];

// ---------------------------------------------------------------------------
// Helpers: tf32 mma (3x error-compensated) + cp.async
// ---------------------------------------------------------------------------
__device__ __forceinline__ void mma8(float d[4], const float a[4], const float b[2]) {
    const uint32_t* A = reinterpret_cast<const uint32_t*>(a);
    const uint32_t* B = reinterpret_cast<const uint32_t*>(b);
    asm volatile(
        "mma.sync.aligned.m16n8k8.row.col.f32.tf32.tf32.f32 "
        "{%0,%1,%2,%3}, {%4,%5,%6,%7}, {%8,%9}, {%0,%1,%2,%3};\n"
        : "+f"(d[0]), "+f"(d[1]), "+f"(d[2]), "+f"(d[3])
        : "r"(A[0]), "r"(A[1]), "r"(A[2]), "r"(A[3]), "r"(B[0]), "r"(B[1]));
}

// d += ah*bh + al*bh + ah*bl   (3xTF32: near-fp32 accuracy)
__device__ __forceinline__ void mma3(float d[4], const float ah[4], const float al[4],
                                     const float bh[2], const float bl[2]) {
    mma8(d, ah, bh);
    mma8(d, al, bh);
    mma8(d, ah, bl);
}

__device__ __forceinline__ void split2(float x, float& hi, float& lo) {
    uint32_t hb, lb;
    asm("cvt.rna.tf32.f32 %0, %1;" : "=r"(hb) : "f"(x));
    hi = __uint_as_float(hb);
    float l = x - hi;
    asm("cvt.rna.tf32.f32 %0, %1;" : "=r"(lb) : "f"(l));
    lo = __uint_as_float(lb);
}

__device__ __forceinline__ void cpa16(void* smem_ptr, const void* gptr) {
    uint32_t s = (uint32_t)__cvta_generic_to_shared(smem_ptr);
    asm volatile("cp.async.cg.shared.global [%0], [%1], 16;\n" :: "r"(s), "l"(gptr));
}
__device__ __forceinline__ void cpa_commit() {
    asm volatile("cp.async.commit_group;\n");
}
template <int N>
__device__ __forceinline__ void cpa_wait() {
    asm volatile("cp.async.wait_group %0;\n" :: "n"(N));
}

// ---------------------------------------------------------------------------
// GEMM: C[m][n] = sum_k A[m][k]*Bw[n][k] + bias[n]   (3xTF32 tensor cores)
// 128x128x32 tiles, 256 threads, 8 warps (2m x 4n), warp tile 64x32.
// Smem stride 36 floats -> fragment LDS bank = 4g+q = lane (conflict-free).
// ---------------------------------------------------------------------------
#define GBK     32
#define GSTRIDE 36
#define GTILE   (128 * GSTRIDE)   // floats per buffer per tensor

__global__ void __launch_bounds__(256) gemm_bt_bias(
    const float* __restrict__ A, const float* __restrict__ Bw,
    const float* __restrict__ bias, float* __restrict__ C,
    int M, int N, int K)
{
    extern __shared__ float sm[];
    float* As = sm;               // 2 buffers
    float* Bs = sm + 2 * GTILE;   // 2 buffers

    const int tid  = threadIdx.x;
    const int lane = tid & 31;
    const int wid  = tid >> 5;
    const int g    = lane >> 2;
    const int q    = lane & 3;
    const int wm   = wid >> 2;    // 0..1
    const int wn   = wid & 3;     // 0..3
    const int bm   = blockIdx.y * 128;
    const int bn   = blockIdx.x * 128;

    float acc[4][4][4] = {};

    auto issue = [&](int t, int buf) {
        const int k0 = t * GBK;
        float* ad = As + buf * GTILE;
        float* bd = Bs + buf * GTILE;
#pragma unroll
        for (int i = 0; i < 4; i++) {
            int idx = tid + i * 256;          // 1024 float4s per tensor
            int row = idx >> 3;
            int c4  = idx & 7;
            cpa16(&ad[row * GSTRIDE + c4 * 4],
                  &A[(size_t)(bm + row) * K + k0 + c4 * 4]);
            cpa16(&bd[row * GSTRIDE + c4 * 4],
                  &Bw[(size_t)(bn + row) * K + k0 + c4 * 4]);
        }
    };

    const int NT = K / GBK;   // 32
    issue(0, 0);
    cpa_commit();

    for (int t = 0; t < NT; t++) {
        if (t + 1 < NT) {
            issue(t + 1, (t + 1) & 1);
            cpa_commit();
            cpa_wait<1>();
        } else {
            cpa_wait<0>();
        }
        __syncthreads();

        const float* as = As + (t & 1) * GTILE;
        const float* bs = Bs + (t & 1) * GTILE;
#pragma unroll
        for (int ks = 0; ks < 4; ks++) {
            const int kb = ks * 8;
            float ah[4][4], al[4][4];
#pragma unroll
            for (int mt = 0; mt < 4; mt++) {
                int base = (wm * 64 + mt * 16 + g) * GSTRIDE + kb + q;
                split2(as[base],                  ah[mt][0], al[mt][0]);
                split2(as[base + 8 * GSTRIDE],    ah[mt][1], al[mt][1]);
                split2(as[base + 4],              ah[mt][2], al[mt][2]);
                split2(as[base + 8 * GSTRIDE + 4],ah[mt][3], al[mt][3]);
            }
            float bh[4][2], bl[4][2];
#pragma unroll
            for (int nt = 0; nt < 4; nt++) {
                int base = (wn * 32 + nt * 8 + g) * GSTRIDE + kb + q;
                split2(bs[base],     bh[nt][0], bl[nt][0]);
                split2(bs[base + 4], bh[nt][1], bl[nt][1]);
            }
#pragma unroll
            for (int mt = 0; mt < 4; mt++)
#pragma unroll
                for (int nt = 0; nt < 4; nt++)
                    mma3(acc[mt][nt], ah[mt], al[mt], bh[nt], bl[nt]);
        }
        __syncthreads();
    }

    // epilogue
#pragma unroll
    for (int mt = 0; mt < 4; mt++) {
        int row0 = bm + wm * 64 + mt * 16 + g;
#pragma unroll
        for (int nt = 0; nt < 4; nt++) {
            int col = bn + wn * 32 + nt * 8 + 2 * q;
            float b0 = bias[col], b1 = bias[col + 1];
            float2 r0 = { acc[mt][nt][0] + b0, acc[mt][nt][1] + b1 };
            float2 r1 = { acc[mt][nt][2] + b0, acc[mt][nt][3] + b1 };
            *(float2*)&C[(size_t)row0 * N + col]       = r0;
            *(float2*)&C[(size_t)(row0 + 8) * N + col] = r1;
        }
    }
}

// ---------------------------------------------------------------------------
// Causal flash attention, 3xTF32 tensor cores.
// Grid (T/64, B*H). 128 threads = 4 warps; each warp owns 16 query rows.
// Q hi/lo fragments hoisted to registers; K/V double-buffered via cp.async;
// P routed through padded smem (stride 76 -> conflict-free frag reloads).
// ---------------------------------------------------------------------------
#define QSTR 68
#define KSTR 68
#define VSTR 72
#define PSTR 76
#define Q_OFF 0
#define P_OFF (64 * QSTR)                     // 4352
#define K_OFF (P_OFF + 64 * PSTR)             // 9216
#define V_OFF (K_OFF + 2 * 64 * KSTR)         // 17920
#define ATTN_SMEM_FLOATS (V_OFF + 2 * 64 * VSTR)  // 27136
#define KBUF(b) (K_OFF + (b) * 64 * KSTR)
#define VBUF(b) (V_OFF + (b) * 64 * VSTR)

__global__ void __launch_bounds__(128) attn_causal()
{
    extern __shared__ float sm[];

    const int qb = blockIdx.x;          // query block (64 rows)
    const int bh = blockIdx.y;
    const int b  = bh / N_HEADS;
    const int h  = bh % N_HEADS;

    const int tid  = threadIdx.x;
    const int lane = tid & 31;
    const int wq   = tid >> 5;          // warp -> 16-row slice
    const int g    = lane >> 2;
    const int q    = lane & 3;

    const float scale = 0.125f;

    const float* Qg = g_Q + (size_t)(b * T_SEQ) * D_MODEL + h * D_KH;
    const float* Kg = g_K + (size_t)(b * T_SEQ) * D_MODEL + h * D_KH;
    const float* Vg = g_V + (size_t)(b * T_SEQ) * D_MODEL + h * D_KH;

    auto stage_kv = [&](int kb, int buf) {
        float* kd = sm + KBUF(buf);
        float* vd = sm + VBUF(buf);
#pragma unroll
        for (int i = 0; i < 8; i++) {
            int idx = tid + i * 128;    // 1024 float4s
            int row = idx >> 4;
            int c4  = idx & 15;
            cpa16(&kd[row * KSTR + c4 * 4],
                  &Kg[(size_t)(kb * 64 + row) * D_MODEL + c4 * 4]);
            cpa16(&vd[row * VSTR + c4 * 4],
                  &Vg[(size_t)(kb * 64 + row) * D_MODEL + c4 * 4]);
        }
    };

    // stage Q (group 0), stage KV block 0 (group 1)
    {
        float* qd = sm + Q_OFF;
#pragma unroll
        for (int i = 0; i < 8; i++) {
            int idx = tid + i * 128;
            int row = idx >> 4;
            int c4  = idx & 15;
            cpa16(&qd[row * QSTR + c4 * 4],
                  &Qg[(size_t)(qb * 64 + row) * D_MODEL + c4 * 4]);
        }
        cpa_commit();
        stage_kv(0, 0);
        cpa_commit();
    }

    // wait for Q, load + split Q fragments (held for the whole kernel)
    cpa_wait<1>();
    __syncthreads();
    float qh[8][4], ql[8][4];
    {
        const float* qs = sm + Q_OFF;
#pragma unroll
        for (int kt = 0; kt < 8; kt++) {
            int base = (wq * 16 + g) * QSTR + kt * 8 + q;
            split2(qs[base],                 qh[kt][0], ql[kt][0]);
            split2(qs[base + 8 * QSTR],      qh[kt][1], ql[kt][1]);
            split2(qs[base + 4],             qh[kt][2], ql[kt][2]);
            split2(qs[base + 8 * QSTR + 4],  qh[kt][3], ql[kt][3]);
        }
    }

    float of[8][4] = {};
    float m0 = -INFINITY, m1 = -INFINITY, l0 = 0.f, l1 = 0.f;

    for (int kb = 0; kb <= qb; kb++) {
        if (kb + 1 <= qb) {
            stage_kv(kb + 1, (kb + 1) & 1);
            cpa_commit();
            cpa_wait<1>();
        } else {
            cpa_wait<0>();
        }
        __syncthreads();

        const float* ks = sm + KBUF(kb & 1);
        const float* vs = sm + VBUF(kb & 1);

        // S = Q K^T  (16x64 per warp), 3xTF32
        float sf[8][4] = {};
#pragma unroll
        for (int kt = 0; kt < 8; kt++) {
#pragma unroll
            for (int nt = 0; nt < 8; nt++) {
                float bhf[2], blf[2];
                int base = (nt * 8 + g) * KSTR + kt * 8 + q;
                split2(ks[base],     bhf[0], blf[0]);
                split2(ks[base + 4], bhf[1], blf[1]);
                mma3(sf[nt], qh[kt], ql[kt], bhf, blf);
            }
        }

        // mask (diagonal block only) + scale
        if (kb == qb) {
            int r0 = wq * 16 + g, r1 = r0 + 8;
#pragma unroll
            for (int nt = 0; nt < 8; nt++) {
                int c0 = nt * 8 + 2 * q, c1 = c0 + 1;
                if (c0 > r0) sf[nt][0] = -INFINITY;
                if (c1 > r0) sf[nt][1] = -INFINITY;
                if (c0 > r1) sf[nt][2] = -INFINITY;
                if (c1 > r1) sf[nt][3] = -INFINITY;
            }
        }
#pragma unroll
        for (int nt = 0; nt < 8; nt++) {
            sf[nt][0] *= scale; sf[nt][1] *= scale;
            sf[nt][2] *= scale; sf[nt][3] *= scale;
        }

        // online softmax (rows g and g+8 of the warp's 16)
        float mx0 = -INFINITY, mx1 = -INFINITY;
#pragma unroll
        for (int nt = 0; nt < 8; nt++) {
            mx0 = fmaxf(mx0, fmaxf(sf[nt][0], sf[nt][1]));
            mx1 = fmaxf(mx1, fmaxf(sf[nt][2], sf[nt][3]));
        }
        mx0 = fmaxf(mx0, __shfl_xor_sync(0xffffffffu, mx0, 1));
        mx0 = fmaxf(mx0, __shfl_xor_sync(0xffffffffu, mx0, 2));
        mx1 = fmaxf(mx1, __shfl_xor_sync(0xffffffffu, mx1, 1));
        mx1 = fmaxf(mx1, __shfl_xor_sync(0xffffffffu, mx1, 2));

        float mn0 = fmaxf(m0, mx0), mn1 = fmaxf(m1, mx1);
        float c0 = __expf(m0 - mn0), c1 = __expf(m1 - mn1);
        m0 = mn0; m1 = mn1;

        float ls0 = 0.f, ls1 = 0.f;
        float* ps = sm + P_OFF;
#pragma unroll
        for (int nt = 0; nt < 8; nt++) {
            float p0 = __expf(sf[nt][0] - mn0);
            float p1 = __expf(sf[nt][1] - mn0);
            float p2 = __expf(sf[nt][2] - mn1);
            float p3 = __expf(sf[nt][3] - mn1);
            ls0 += p0 + p1; ls1 += p2 + p3;
            int col = nt * 8 + 2 * q;
            *(float2*)&ps[(wq * 16 + g) * PSTR + col]     = make_float2(p0, p1);
            *(float2*)&ps[(wq * 16 + g + 8) * PSTR + col] = make_float2(p2, p3);
            of[nt][0] *= c0; of[nt][1] *= c0;
            of[nt][2] *= c1; of[nt][3] *= c1;
        }
        ls0 += __shfl_xor_sync(0xffffffffu, ls0, 1);
        ls0 += __shfl_xor_sync(0xffffffffu, ls0, 2);
        ls1 += __shfl_xor_sync(0xffffffffu, ls1, 1);
        ls1 += __shfl_xor_sync(0xffffffffu, ls1, 2);
        l0 = l0 * c0 + ls0;
        l1 = l1 * c1 + ls1;
        __syncwarp();

        // O += P V  (3xTF32)
#pragma unroll
        for (int jt = 0; jt < 8; jt++) {
            float pah[4], pal[4];
            int pb = (wq * 16 + g) * PSTR + jt * 8 + q;
            split2(ps[pb],                pah[0], pal[0]);
            split2(ps[pb + 8 * PSTR],     pah[1], pal[1]);
            split2(ps[pb + 4],            pah[2], pal[2]);
            split2(ps[pb + 8 * PSTR + 4], pah[3], pal[3]);
#pragma unroll
            for (int nt = 0; nt < 8; nt++) {
                float vbh[2], vbl[2];
                int base = (jt * 8 + q) * VSTR + nt * 8 + g;
                split2(vs[base],            vbh[0], vbl[0]);
                split2(vs[base + 4 * VSTR], vbh[1], vbl[1]);
                mma3(of[nt], pah, pal, vbh, vbl);
            }
        }
        __syncthreads();
    }

    // normalize + store (heads re-merged)
    float inv0 = 1.0f / l0, inv1 = 1.0f / l1;
    int row0 = qb * 64 + wq * 16 + g;
    float* dst0 = g_O + (size_t)(b * T_SEQ + row0) * D_MODEL + h * D_KH;
    float* dst1 = dst0 + 8 * D_MODEL;
#pragma unroll
    for (int nt = 0; nt < 8; nt++) {
        int col = nt * 8 + 2 * q;
        *(float2*)&dst0[col] = make_float2(of[nt][0] * inv0, of[nt][1] * inv0);
        *(float2*)&dst1[col] = make_float2(of[nt][2] * inv1, of[nt][3] * inv1);
    }
}

// ---------------------------------------------------------------------------
extern "C" void kernel_launch(void* const* d_in, const int* in_sizes, int n_in,
                              void* d_out, int out_size)
{
    const float* q   = (const float*)d_in[0];
    const float* k   = (const float*)d_in[1];
    const float* v   = (const float*)d_in[2];
    // d_in[3] = mask (bool causal tril) — causality hardcoded in attn_causal
    const float* W_q = (const float*)d_in[4];
    const float* b_q = (const float*)d_in[5];
    const float* W_k = (const float*)d_in[6];
    const float* b_k = (const float*)d_in[7];
    const float* W_v = (const float*)d_in[8];
    const float* b_v = (const float*)d_in[9];
    const float* W_o = (const float*)d_in[10];
    const float* b_o = (const float*)d_in[11];
    float* out = (float*)d_out;

    float *pQ, *pK, *pV, *pO;
    cudaGetSymbolAddress((void**)&pQ, g_Q);
    cudaGetSymbolAddress((void**)&pK, g_K);
    cudaGetSymbolAddress((void**)&pV, g_V);
    cudaGetSymbolAddress((void**)&pO, g_O);

    const int gemm_smem = 4 * GTILE * (int)sizeof(float);          // 73728
    const int attn_smem = ATTN_SMEM_FLOATS * (int)sizeof(float);   // 108544
    cudaFuncSetAttribute(gemm_bt_bias, cudaFuncAttributeMaxDynamicSharedMemorySize,
                         gemm_smem);
    cudaFuncSetAttribute(attn_causal, cudaFuncAttributeMaxDynamicSharedMemorySize,
                         attn_smem);

    dim3 gGrid(D_MODEL / 128, M_ROWS / 128);   // (8, 64)
    gemm_bt_bias<<<gGrid, 256, gemm_smem>>>(q, W_q, b_q, pQ, M_ROWS, D_MODEL, D_MODEL);
    gemm_bt_bias<<<gGrid, 256, gemm_smem>>>(k, W_k, b_k, pK, M_ROWS, D_MODEL, D_MODEL);
    gemm_bt_bias<<<gGrid, 256, gemm_smem>>>(v, W_v, b_v, pV, M_ROWS, D_MODEL, D_MODEL);

    dim3 aGrid(T_SEQ / 64, B_SZ * N_HEADS);    // (32, 64)
    attn_causal<<<aGrid, 128, attn_smem>>>();

    gemm_bt_bias<<<gGrid, 256, gemm_smem>>>(pO, W_o, b_o, out, M_ROWS, D_MODEL, D_MODEL);
}